// round 1
// baseline (speedup 1.0000x reference)
#include <cuda_runtime.h>
#include <cuda_fp16.h>
#include <cstdint>

// Problem constants
#define TOKENS 32768          // B*S = 16*2048
#define FDIM   1024
#define NQKV   3072
#define NHEAD  16
#define DHEAD  64

// ---------------------------------------------------------------------------
// Scratch (device globals; no allocations allowed)
// ---------------------------------------------------------------------------
__device__ __align__(16) half  g_X16 [(size_t)TOKENS * FDIM];   // x in fp16
__device__ __align__(16) half  g_Wqkv[(size_t)FDIM * NQKV];     // packed [Wq|Wk|Wv] fp16
__device__ __align__(16) half  g_Wo16[(size_t)FDIM * FDIM];     // Wo fp16
__device__ float               g_bqkv[NQKV];                    // packed biases
__device__ __align__(16) half  g_QKV [(size_t)TOKENS * NQKV];   // q,k,v per token
__device__ __align__(16) half  g_Attn[(size_t)TOKENS * FDIM];   // attention output
__device__ __align__(16) float g_Z   [(size_t)TOKENS * FDIM];   // pre-LN output

// ---------------------------------------------------------------------------
// PTX helpers
// ---------------------------------------------------------------------------
__device__ __forceinline__ void cp_async16(void* dst, const void* src){
    unsigned s = (unsigned)__cvta_generic_to_shared(dst);
    asm volatile("cp.async.cg.shared.global [%0], [%1], 16;\n" :: "r"(s), "l"(src));
}
__device__ __forceinline__ void cp_commit(){ asm volatile("cp.async.commit_group;\n"); }
__device__ __forceinline__ void cp_wait1(){ asm volatile("cp.async.wait_group 1;\n"); }

__device__ __forceinline__ void ldsm_x4(uint32_t* r, uint32_t addr){
    asm volatile("ldmatrix.sync.aligned.m8n8.x4.shared.b16 {%0,%1,%2,%3}, [%4];\n"
        : "=r"(r[0]), "=r"(r[1]), "=r"(r[2]), "=r"(r[3]) : "r"(addr));
}
__device__ __forceinline__ void ldsm_x4_t(uint32_t* r, uint32_t addr){
    asm volatile("ldmatrix.sync.aligned.m8n8.x4.trans.shared.b16 {%0,%1,%2,%3}, [%4];\n"
        : "=r"(r[0]), "=r"(r[1]), "=r"(r[2]), "=r"(r[3]) : "r"(addr));
}
__device__ __forceinline__ void mma16816(float* c, const uint32_t* a, const uint32_t* b){
    asm volatile("mma.sync.aligned.m16n8k16.row.col.f32.f16.f16.f32 "
        "{%0,%1,%2,%3}, {%4,%5,%6,%7}, {%8,%9}, {%0,%1,%2,%3};\n"
        : "+f"(c[0]), "+f"(c[1]), "+f"(c[2]), "+f"(c[3])
        : "r"(a[0]), "r"(a[1]), "r"(a[2]), "r"(a[3]), "r"(b[0]), "r"(b[1]));
}

// ---------------------------------------------------------------------------
// Convert kernels
// ---------------------------------------------------------------------------
__global__ void __launch_bounds__(256) convx_kernel(const float* __restrict__ x){
    const size_t n4 = (size_t)TOKENS * FDIM / 4;
    size_t stride = (size_t)gridDim.x * blockDim.x;
    for (size_t i = (size_t)blockIdx.x * blockDim.x + threadIdx.x; i < n4; i += stride){
        float4 v = ((const float4*)x)[i];
        ((half2*)g_X16)[2*i]   = __floats2half2_rn(v.x, v.y);
        ((half2*)g_X16)[2*i+1] = __floats2half2_rn(v.z, v.w);
    }
}

__global__ void __launch_bounds__(256) convw_kernel(
    const float* __restrict__ Wq, const float* __restrict__ Wk, const float* __restrict__ Wv,
    const float* __restrict__ Wo, const float* __restrict__ bq, const float* __restrict__ bk,
    const float* __restrict__ bv)
{
    int gid = blockIdx.x * blockDim.x + threadIdx.x;
    int stride = gridDim.x * blockDim.x;
    const int WSZ = 1024 * 1024;
    for (int i = gid; i < 4 * WSZ; i += stride){
        if (i < 3 * WSZ){
            int w = i >> 20;
            int j = i & (WSZ - 1);
            int k = j >> 10, n = j & 1023;
            const float* W = (w == 0) ? Wq : ((w == 1) ? Wk : Wv);
            g_Wqkv[(size_t)k * NQKV + w * 1024 + n] = __float2half_rn(W[j]);
        } else {
            int j = i - 3 * WSZ;
            g_Wo16[j] = __float2half_rn(Wo[j]);
        }
    }
    if (gid < NQKV){
        g_bqkv[gid] = (gid < 1024) ? bq[gid] : (gid < 2048) ? bk[gid - 1024] : bv[gid - 2048];
    }
}

// ---------------------------------------------------------------------------
// GEMM: C[M,N] = A[M,1024] * B[1024,N] + bias, fp16 inputs, fp32 accumulate.
// MODE 0: A=g_X16, B=g_Wqkv (N=3072), bias=g_bqkv, C=g_QKV (half)
// MODE 1: A=g_Attn, B=g_Wo16 (N=1024), bias=arg,   C=g_Z   (float)
// Tile 128x128x32, 8 warps (2x4), warp tile 64x32, cp.async double buffer.
// SMEM row strides padded: A 40 halfs (80B), B 136 halfs (272B) -> ldmatrix
// granule strides 5 and 17 (coprime with 8) => conflict-free.
// ---------------------------------------------------------------------------
template<int MODE>
__global__ void __launch_bounds__(256, 2) gemm_kernel(const float* __restrict__ bias_ext){
    constexpr int N = (MODE == 0) ? NQKV : FDIM;
    const half* A = (MODE == 0) ? g_X16 : g_Attn;
    const half* B = (MODE == 0) ? g_Wqkv : g_Wo16;

    __shared__ half As[2][128 * 40];
    __shared__ half Bs[2][32 * 136];

    const int tid  = threadIdx.x;
    const int lane = tid & 31;
    const int wid  = tid >> 5;
    const int wm   = wid & 1;       // 0..1
    const int wn   = wid >> 1;      // 0..3
    const int m0 = blockIdx.y * 128;
    const int n0 = blockIdx.x * 128;

    const half* Ag = A + (size_t)m0 * FDIM;
    const half* Bg = B + n0;

    float acc[4][4][4];
    #pragma unroll
    for (int mi = 0; mi < 4; ++mi)
        #pragma unroll
        for (int ni = 0; ni < 4; ++ni)
            #pragma unroll
            for (int t = 0; t < 4; ++t) acc[mi][ni][t] = 0.f;

    auto load_stage = [&](int buf, int s){
        int k0 = s * 32;
        #pragma unroll
        for (int i = 0; i < 2; ++i){
            int c = tid + i * 256;
            int r  = c >> 2, ch = c & 3;
            cp_async16(&As[buf][r * 40 + ch * 8], Ag + (size_t)r * FDIM + k0 + ch * 8);
            int rb = c >> 4, cb = c & 15;
            cp_async16(&Bs[buf][rb * 136 + cb * 8], Bg + (size_t)(k0 + rb) * N + cb * 8);
        }
    };

    load_stage(0, 0);
    cp_commit();

    const int NK = FDIM / 32; // 32
    for (int s = 0; s < NK; ++s){
        if (s + 1 < NK) load_stage((s + 1) & 1, s + 1);
        cp_commit();
        cp_wait1();
        __syncthreads();

        int buf = s & 1;
        uint32_t aB = (uint32_t)__cvta_generic_to_shared(&As[buf][0]);
        uint32_t bB = (uint32_t)__cvta_generic_to_shared(&Bs[buf][0]);

        #pragma unroll
        for (int kk = 0; kk < 2; ++kk){
            const int k16 = kk * 16;
            uint32_t a[4][4], bfr[4][2];
            #pragma unroll
            for (int mi = 0; mi < 4; ++mi){
                int row = wm * 64 + mi * 16 + (lane & 15);
                uint32_t addr = aB + (uint32_t)((row * 40 + k16 + ((lane >> 4) << 3)) * 2);
                ldsm_x4(&a[mi][0], addr);
            }
            #pragma unroll
            for (int nb = 0; nb < 2; ++nb){
                int row = k16 + (lane & 7) + (((lane >> 3) & 1) << 3);
                int col = wn * 32 + nb * 16 + (((lane >> 4) & 1) << 3);
                uint32_t r[4];
                ldsm_x4_t(r, bB + (uint32_t)((row * 136 + col) * 2));
                bfr[nb * 2][0] = r[0]; bfr[nb * 2][1] = r[1];
                bfr[nb * 2 + 1][0] = r[2]; bfr[nb * 2 + 1][1] = r[3];
            }
            #pragma unroll
            for (int mi = 0; mi < 4; ++mi)
                #pragma unroll
                for (int ni = 0; ni < 4; ++ni)
                    mma16816(acc[mi][ni], a[mi], bfr[ni]);
        }
        __syncthreads();
    }

    // epilogue: +bias, store
    const float* bias = (MODE == 0) ? g_bqkv : bias_ext;
    #pragma unroll
    for (int mi = 0; mi < 4; ++mi){
        #pragma unroll
        for (int ni = 0; ni < 4; ++ni){
            int r = m0 + wm * 64 + mi * 16 + (lane >> 2);
            int c = n0 + wn * 32 + ni * 8 + ((lane & 3) << 1);
            float b0 = bias[c], b1 = bias[c + 1];
            float v0 = acc[mi][ni][0] + b0, v1 = acc[mi][ni][1] + b1;
            float v2 = acc[mi][ni][2] + b0, v3 = acc[mi][ni][3] + b1;
            if constexpr (MODE == 0){
                *(half2*)(g_QKV + (size_t)r * N + c)       = __floats2half2_rn(v0, v1);
                *(half2*)(g_QKV + (size_t)(r + 8) * N + c) = __floats2half2_rn(v2, v3);
            } else {
                *(float2*)(g_Z + (size_t)r * N + c)       = make_float2(v0, v1);
                *(float2*)(g_Z + (size_t)(r + 8) * N + c) = make_float2(v2, v3);
            }
        }
    }
}

// ---------------------------------------------------------------------------
// Per-token cross-head attention. 1 warp per token, 8 tokens per block.
// energy[h][g] = q[h].k[g]/8 ; softmax over g ; out[h] = sum_g p[g] v[g].
// Lane l: h = l/2, owns 8 of 16 g's. Rotation (j+h)&31 keeps SMEM reads
// bank-conflict-free with compile-time register indices (dot is order-invariant).
// ---------------------------------------------------------------------------
__global__ void __launch_bounds__(256) attn_kernel(){
    __shared__ half sq[8][NQKV];   // 48 KB
    const int tid = threadIdx.x, lane = tid & 31, w = tid >> 5;
    const size_t tok0 = (size_t)blockIdx.x * 8;

    // cooperative load 8 tokens x 3072 halfs
    const float4* src = (const float4*)(g_QKV + tok0 * NQKV);
    float4* dstv = (float4*)&sq[0][0];
    #pragma unroll
    for (int i = 0; i < 12; ++i) dstv[tid + i * 256] = src[tid + i * 256];
    __syncthreads();

    const half2* q2 = (const half2*)&sq[w][0];
    const half2* k2 = (const half2*)&sq[w][1024];
    const half2* v2 = (const half2*)&sq[w][2048];
    const int h  = lane >> 1;
    const int gb = (lane & 1) << 3;

    // q row into registers (rotated)
    float2 qr[32];
    #pragma unroll
    for (int j = 0; j < 32; ++j){
        int d = (j + h) & 31;
        qr[j] = __half22float2(q2[h * 32 + d]);
    }

    // energies
    float e[8];
    #pragma unroll
    for (int gi = 0; gi < 8; ++gi){
        int g = gb + gi;
        float a = 0.f;
        #pragma unroll
        for (int j = 0; j < 32; ++j){
            int d = (j + h) & 31;
            float2 kf = __half22float2(k2[g * 32 + d]);
            a += qr[j].x * kf.x + qr[j].y * kf.y;
        }
        e[gi] = a * 0.125f;
    }

    // softmax over 16 g's split across the lane pair
    float m = e[0];
    #pragma unroll
    for (int gi = 1; gi < 8; ++gi) m = fmaxf(m, e[gi]);
    m = fmaxf(m, __shfl_xor_sync(0xffffffffu, m, 1));
    float ssum = 0.f;
    #pragma unroll
    for (int gi = 0; gi < 8; ++gi){ e[gi] = __expf(e[gi] - m); ssum += e[gi]; }
    ssum += __shfl_xor_sync(0xffffffffu, ssum, 1);
    float inv = 1.f / ssum;

    // out partials over own 8 g's, all 64 d
    float2 o[32];
    #pragma unroll
    for (int j = 0; j < 32; ++j) o[j] = make_float2(0.f, 0.f);
    #pragma unroll
    for (int gi = 0; gi < 8; ++gi){
        float p = e[gi] * inv;
        int g = gb + gi;
        #pragma unroll
        for (int j = 0; j < 32; ++j){
            int d = (j + h) & 31;
            float2 vf = __half22float2(v2[g * 32 + d]);
            o[j].x += p * vf.x; o[j].y += p * vf.y;
        }
    }
    // pair reduce (same h, same rotation)
    #pragma unroll
    for (int j = 0; j < 32; ++j){
        o[j].x += __shfl_xor_sync(0xffffffffu, o[j].x, 1);
        o[j].y += __shfl_xor_sync(0xffffffffu, o[j].y, 1);
    }
    __syncwarp();

    // even lanes stash results in the (now dead) q region, conflict-free
    half2* outs = (half2*)&sq[w][0];
    if ((lane & 1) == 0){
        #pragma unroll
        for (int j = 0; j < 32; ++j){
            int d = (j + h) & 31;
            outs[h * 32 + d] = __floats2half2_rn(o[j].x, o[j].y);
        }
    }
    __syncthreads();

    // coalesced store: 8 tokens x 1024 halfs
    float4* gout = (float4*)(g_Attn + tok0 * FDIM);
    #pragma unroll
    for (int i = 0; i < 4; ++i){
        int c = tid + i * 256;          // 0..1023 chunks of 8 halfs
        int tw = c >> 7, off = c & 127;
        gout[c] = *(const float4*)(&sq[tw][off * 8]);
    }
}

// ---------------------------------------------------------------------------
// LayerNorm over F=1024, one block per row
// ---------------------------------------------------------------------------
__global__ void __launch_bounds__(256) ln_kernel(const float* __restrict__ gamma,
                                                 const float* __restrict__ beta,
                                                 float* __restrict__ out)
{
    const int row = blockIdx.x, t = threadIdx.x, lane = t & 31, wid = t >> 5;
    float4 v = ((const float4*)(g_Z + (size_t)row * FDIM))[t];
    float s = v.x + v.y + v.z + v.w;
    float q = v.x * v.x + v.y * v.y + v.z * v.z + v.w * v.w;
    #pragma unroll
    for (int o = 16; o > 0; o >>= 1){
        s += __shfl_xor_sync(0xffffffffu, s, o);
        q += __shfl_xor_sync(0xffffffffu, q, o);
    }
    __shared__ float ws[8], wq[8], mv[2];
    if (lane == 0){ ws[wid] = s; wq[wid] = q; }
    __syncthreads();
    if (t == 0){
        float S = 0.f, Q = 0.f;
        #pragma unroll
        for (int i = 0; i < 8; ++i){ S += ws[i]; Q += wq[i]; }
        float mean = S * (1.f / 1024.f);
        float var  = Q * (1.f / 1024.f) - mean * mean;
        mv[0] = mean; mv[1] = rsqrtf(var + 1e-5f);
    }
    __syncthreads();
    float mean = mv[0], rstd = mv[1];
    float4 g4 = ((const float4*)gamma)[t];
    float4 b4 = ((const float4*)beta)[t];
    float4 r;
    r.x = (v.x - mean) * rstd * g4.x + b4.x;
    r.y = (v.y - mean) * rstd * g4.y + b4.y;
    r.z = (v.z - mean) * rstd * g4.z + b4.z;
    r.w = (v.w - mean) * rstd * g4.w + b4.w;
    ((float4*)(out + (size_t)row * FDIM))[t] = r;
}

// ---------------------------------------------------------------------------
// Launch
// ---------------------------------------------------------------------------
extern "C" void kernel_launch(void* const* d_in, const int* in_sizes, int n_in,
                              void* d_out, int out_size)
{
    (void)in_sizes; (void)n_in; (void)out_size;
    const float* x     = (const float*)d_in[0];
    const float* Wq    = (const float*)d_in[1];
    const float* bq    = (const float*)d_in[2];
    const float* Wk    = (const float*)d_in[3];
    const float* bk    = (const float*)d_in[4];
    const float* Wv    = (const float*)d_in[5];
    const float* bv    = (const float*)d_in[6];
    const float* Wo    = (const float*)d_in[7];
    const float* bo    = (const float*)d_in[8];
    const float* gamma = (const float*)d_in[9];
    const float* beta  = (const float*)d_in[10];
    float* out = (float*)d_out;

    convx_kernel<<<4096, 256>>>(x);
    convw_kernel<<<2048, 256>>>(Wq, Wk, Wv, Wo, bq, bk, bv);
    gemm_kernel<0><<<dim3(NQKV / 128, TOKENS / 128), 256>>>(nullptr);
    attn_kernel<<<TOKENS / 8, 256>>>();
    gemm_kernel<1><<<dim3(FDIM / 128, TOKENS / 128), 256>>>(bo);
    ln_kernel<<<TOKENS, 256>>>(gamma, beta, out);
}